// round 5
// baseline (speedup 1.0000x reference)
#include <cuda_runtime.h>
#include <cstdint>

// ERGCN layer:
//   msg[k] = h[src[k]] * weight[rel[k]] + e[k] * attention[rel[k]]   (elementwise, D=64)
//   out    = h + segment_sum(msg, dst)
//
// Inputs (metadata order): h[N*64] f32, e[E*64] f32, weight[R*64] f32,
// attention[R*64] f32, src[E] i32, dst[E] i32, rel[E] i32. Output: [N*64] f32.

#define D 64
#define D4 (D / 4)            // 16 float4 per row
#define TPB 256
#define EDGES_PER_BLK (TPB / D4)   // 16 edges processed per block-iteration

// ---------------------------------------------------------------------------
// Kernel 1: out = h  (vectorized copy; d_out is poisoned before timing)
// ---------------------------------------------------------------------------
__global__ void init_out_kernel(float4* __restrict__ out,
                                const float4* __restrict__ h,
                                int n4) {
    int i = blockIdx.x * blockDim.x + threadIdx.x;
    if (i < n4) out[i] = h[i];
}

// ---------------------------------------------------------------------------
// Kernel 2: per-edge message + vectorized atomic scatter.
// 16 threads per edge; weight+attention tables staged in shared memory.
// Persistent grid-stride so the 102.4KB smem staging is amortized.
// ---------------------------------------------------------------------------
__global__ void __launch_bounds__(TPB, 2)
edge_kernel(const float* __restrict__ h,
            const float* __restrict__ e,
            const float4* __restrict__ w_g,
            const float4* __restrict__ a_g,
            const int* __restrict__ src,
            const int* __restrict__ dst,
            const int* __restrict__ rel,
            float* __restrict__ out,
            int E_, int R4 /* = R * D4 */) {
    extern __shared__ float4 s4[];          // [0, R4) weight, [R4, 2*R4) attention

    for (int i = threadIdx.x; i < R4; i += TPB) s4[i] = w_g[i];
    for (int i = threadIdx.x; i < R4; i += TPB) s4[R4 + i] = a_g[i];
    __syncthreads();

    const int group = threadIdx.x >> 4;     // 0..15: which edge in the tile
    const int t     = threadIdx.x & 15;     // 0..15: which float4 of the row
    const int stride = gridDim.x * EDGES_PER_BLK;

    for (int k = blockIdx.x * EDGES_PER_BLK + group; k < E_; k += stride) {
        const int s_ = __ldg(src + k);
        const int d_ = __ldg(dst + k);
        const int r_ = __ldg(rel + k);

        const float4 hv = __ldg((const float4*)(h + (size_t)s_ * D) + t);
        const float4 ev = __ldg((const float4*)(e + (size_t)k  * D) + t);
        const float4 wv = s4[r_ * D4 + t];
        const float4 av = s4[R4 + r_ * D4 + t];

        float4 m;
        m.x = fmaf(hv.x, wv.x, ev.x * av.x);
        m.y = fmaf(hv.y, wv.y, ev.y * av.y);
        m.z = fmaf(hv.z, wv.z, ev.z * av.z);
        m.w = fmaf(hv.w, wv.w, ev.w * av.w);

        float* o = out + (size_t)d_ * D + t * 4;
        asm volatile("red.global.add.v4.f32 [%0], {%1, %2, %3, %4};"
                     :: "l"(o), "f"(m.x), "f"(m.y), "f"(m.z), "f"(m.w)
                     : "memory");
    }
}

extern "C" void kernel_launch(void* const* d_in, const int* in_sizes, int n_in,
                              void* d_out, int out_size) {
    const float* h   = (const float*)d_in[0];
    const float* e   = (const float*)d_in[1];
    const float* wgt = (const float*)d_in[2];
    const float* att = (const float*)d_in[3];
    const int*   src = (const int*)d_in[4];
    const int*   dst = (const int*)d_in[5];
    const int*   rel = (const int*)d_in[6];
    float*       out = (float*)d_out;

    const int ND = in_sizes[0];          // N * 64
    const int E_ = in_sizes[4];          // edge count
    const int R_ = in_sizes[2] / D;      // relation count
    const int R4 = R_ * D4;
    const size_t smem = (size_t)2 * R4 * sizeof(float4);   // 102400 B for R=200

    // out = h
    {
        int n4 = ND / 4;
        init_out_kernel<<<(n4 + TPB - 1) / TPB, TPB>>>(
            (float4*)out, (const float4*)h, n4);
    }

    // message + scatter (persistent grid: 2 CTAs/SM × 148 SMs)
    cudaFuncSetAttribute(edge_kernel,
                         cudaFuncAttributeMaxDynamicSharedMemorySize,
                         (int)smem);
    edge_kernel<<<296, TPB, smem>>>(h, e, (const float4*)wgt,
                                    (const float4*)att,
                                    src, dst, rel, out, E_, R4);
}

// round 6
// speedup vs baseline: 1.7844x; 1.7844x over previous
#include <cuda_runtime.h>
#include <cstdint>

// ERGCN layer:
//   msg[k] = h[src[k]] * weight[rel[k]] + e[k] * attention[rel[k]]   (D=64)
//   out    = h + segment_sum(msg, dst)
//
// Inputs: h[N*64] f32, e[E*64] f32, weight[R*64] f32, attention[R*64] f32,
//         src[E] i32, dst[E] i32, rel[E] i32. Output: [N*64] f32.

#define D 64
#define D4 (D / 4)        // 16 float4 per row
#define TPB 256

// ---------------------------------------------------------------------------
// Kernel 1: out = h (d_out is poisoned before timing)
// ---------------------------------------------------------------------------
__global__ void init_out_kernel(float4* __restrict__ out,
                                const float4* __restrict__ h,
                                int n4) {
    int i = blockIdx.x * blockDim.x + threadIdx.x;
    if (i < n4) out[i] = h[i];
}

// ---------------------------------------------------------------------------
// Kernel 2: one 16-lane group per edge; pure TLP, no loop.
// Tables read through L1 (51.2 KB, fully resident). h gather hits L2.
// ---------------------------------------------------------------------------
__global__ void __launch_bounds__(TPB)
edge_kernel(const float* __restrict__ h,
            const float* __restrict__ e,
            const float4* __restrict__ w_g,
            const float4* __restrict__ a_g,
            const int* __restrict__ src,
            const int* __restrict__ dst,
            const int* __restrict__ rel,
            float* __restrict__ out,
            int E_) {
    const int gid = blockIdx.x * TPB + threadIdx.x;
    const int k   = gid >> 4;          // edge index
    const int t   = gid & 15;          // float4 index within the 64-float row
    if (k >= E_) return;

    const int s_ = __ldg(src + k);
    const int d_ = __ldg(dst + k);
    const int r_ = __ldg(rel + k);

    const float4 ev = __ldg((const float4*)(e + (size_t)k  * D) + t);
    const float4 hv = __ldg((const float4*)(h + (size_t)s_ * D) + t);
    const float4 wv = __ldg(w_g + r_ * D4 + t);
    const float4 av = __ldg(a_g + r_ * D4 + t);

    float4 m;
    m.x = fmaf(hv.x, wv.x, ev.x * av.x);
    m.y = fmaf(hv.y, wv.y, ev.y * av.y);
    m.z = fmaf(hv.z, wv.z, ev.z * av.z);
    m.w = fmaf(hv.w, wv.w, ev.w * av.w);

    float* o = out + (size_t)d_ * D + t * 4;
    asm volatile("red.global.add.v4.f32 [%0], {%1, %2, %3, %4};"
                 :: "l"(o), "f"(m.x), "f"(m.y), "f"(m.z), "f"(m.w)
                 : "memory");
}

extern "C" void kernel_launch(void* const* d_in, const int* in_sizes, int n_in,
                              void* d_out, int out_size) {
    const float* h   = (const float*)d_in[0];
    const float* e   = (const float*)d_in[1];
    const float* wgt = (const float*)d_in[2];
    const float* att = (const float*)d_in[3];
    const int*   src = (const int*)d_in[4];
    const int*   dst = (const int*)d_in[5];
    const int*   rel = (const int*)d_in[6];
    float*       out = (float*)d_out;

    const int ND = in_sizes[0];      // N * 64
    const int E_ = in_sizes[4];      // edge count

    // out = h
    {
        int n4 = ND / 4;
        init_out_kernel<<<(n4 + TPB - 1) / TPB, TPB>>>(
            (float4*)out, (const float4*)h, n4);
    }

    // one 16-lane group per edge
    {
        long long total = (long long)E_ * D4;
        int blocks = (int)((total + TPB - 1) / TPB);
        edge_kernel<<<blocks, TPB>>>(h, e, (const float4*)wgt,
                                     (const float4*)att,
                                     src, dst, rel, out, E_);
    }
}

// round 7
// speedup vs baseline: 2.2269x; 1.2480x over previous
#include <cuda_runtime.h>
#include <cstdint>

// ERGCN layer:
//   msg[k] = h[src[k]] * weight[rel[k]] + e[k] * attention[rel[k]]   (D=64)
//   out    = h + segment_sum(msg, dst)
//
// Inputs: h[N*64] f32, e[E*64] f32, weight[R*64] f32, attention[R*64] f32,
//         src[E] i32, dst[E] i32, rel[E] i32. Output: [N*64] f32.

#define D 64
#define D4 (D / 4)        // 16 float4 per row
#define TPB 256
#define TPE 8             // threads per edge; each handles chunks t and t+8

// Streaming load: bypass L1 allocation (e has zero reuse).
__device__ __forceinline__ float4 ldg_stream(const float4* p) {
    float4 v;
    asm("ld.global.nc.L1::no_allocate.v4.f32 {%0,%1,%2,%3}, [%4];"
        : "=f"(v.x), "=f"(v.y), "=f"(v.z), "=f"(v.w) : "l"(p));
    return v;
}

// ---------------------------------------------------------------------------
// Kernel 1: out = h (d_out is poisoned before timing)
// ---------------------------------------------------------------------------
__global__ void init_out_kernel(float4* __restrict__ out,
                                const float4* __restrict__ h,
                                int n4) {
    int i = blockIdx.x * blockDim.x + threadIdx.x;
    if (i < n4) out[i] = h[i];
}

// ---------------------------------------------------------------------------
// Kernel 2: 8 threads per edge, 2 float4 chunks per thread.
// 8 independent loads in flight per thread; tables stay L1-resident.
// ---------------------------------------------------------------------------
__global__ void __launch_bounds__(TPB)
edge_kernel(const float* __restrict__ h,
            const float* __restrict__ e,
            const float4* __restrict__ w_g,
            const float4* __restrict__ a_g,
            const int* __restrict__ src,
            const int* __restrict__ dst,
            const int* __restrict__ rel,
            float* __restrict__ out,
            int E_) {
    const int gid = blockIdx.x * TPB + threadIdx.x;
    const int k   = gid >> 3;          // edge index
    const int t   = gid & 7;           // chunk index (handles t and t+8)
    if (k >= E_) return;

    const int s_ = __ldg(src + k);
    const int d_ = __ldg(dst + k);
    const int r_ = __ldg(rel + k);

    const float4* ep = (const float4*)(e + (size_t)k  * D) + t;
    const float4* hp = (const float4*)(h + (size_t)s_ * D) + t;
    const float4* wp = w_g + r_ * D4 + t;
    const float4* ap = a_g + r_ * D4 + t;

    const float4 ev0 = ldg_stream(ep);
    const float4 ev1 = ldg_stream(ep + 8);
    const float4 hv0 = __ldg(hp);
    const float4 hv1 = __ldg(hp + 8);
    const float4 wv0 = __ldg(wp);
    const float4 wv1 = __ldg(wp + 8);
    const float4 av0 = __ldg(ap);
    const float4 av1 = __ldg(ap + 8);

    float4 m0, m1;
    m0.x = fmaf(hv0.x, wv0.x, ev0.x * av0.x);
    m0.y = fmaf(hv0.y, wv0.y, ev0.y * av0.y);
    m0.z = fmaf(hv0.z, wv0.z, ev0.z * av0.z);
    m0.w = fmaf(hv0.w, wv0.w, ev0.w * av0.w);
    m1.x = fmaf(hv1.x, wv1.x, ev1.x * av1.x);
    m1.y = fmaf(hv1.y, wv1.y, ev1.y * av1.y);
    m1.z = fmaf(hv1.z, wv1.z, ev1.z * av1.z);
    m1.w = fmaf(hv1.w, wv1.w, ev1.w * av1.w);

    float* o = out + (size_t)d_ * D + t * 4;
    asm volatile("red.global.add.v4.f32 [%0], {%1, %2, %3, %4};"
                 :: "l"(o), "f"(m0.x), "f"(m0.y), "f"(m0.z), "f"(m0.w)
                 : "memory");
    asm volatile("red.global.add.v4.f32 [%0], {%1, %2, %3, %4};"
                 :: "l"(o + 32), "f"(m1.x), "f"(m1.y), "f"(m1.z), "f"(m1.w)
                 : "memory");
}

extern "C" void kernel_launch(void* const* d_in, const int* in_sizes, int n_in,
                              void* d_out, int out_size) {
    const float* h   = (const float*)d_in[0];
    const float* e   = (const float*)d_in[1];
    const float* wgt = (const float*)d_in[2];
    const float* att = (const float*)d_in[3];
    const int*   src = (const int*)d_in[4];
    const int*   dst = (const int*)d_in[5];
    const int*   rel = (const int*)d_in[6];
    float*       out = (float*)d_out;

    const int ND = in_sizes[0];      // N * 64
    const int E_ = in_sizes[4];      // edge count

    // out = h
    {
        int n4 = ND / 4;
        init_out_kernel<<<(n4 + TPB - 1) / TPB, TPB>>>(
            (float4*)out, (const float4*)h, n4);
    }

    // 8 threads per edge
    {
        long long total = (long long)E_ * TPE;
        int blocks = (int)((total + TPB - 1) / TPB);
        edge_kernel<<<blocks, TPB>>>(h, e, (const float4*)wgt,
                                     (const float4*)att,
                                     src, dst, rel, out, E_);
    }
}